// round 9
// baseline (speedup 1.0000x reference)
#include <cuda_runtime.h>
#include <cstdint>
#include <float.h>

#define B_      32
#define S_      4096
#define EH      1024
#define AT      512
#define BM      128
#define BK      32
#define NCHUNK  4
#define BNC     128
#define CHUNKS  (S_/BM)   // 32

// ---------------- scratch (no allocations allowed) ----------------
__device__ float g_pd[B_*AT];           // decoder projection (B,512)
__device__ float g_scores[B_*S_];       // masked scores
__device__ float g_ctx[B_*CHUNKS*EH];   // per-chunk context partials (4MB)
__device__ float g_lmax[B_*CHUNKS];
__device__ float g_lsum[B_*CHUNKS];
__device__ float g_gmax[B_];
__device__ float g_invZ[B_];

// ---------------- helpers ----------------
__device__ __forceinline__ unsigned f2tf(float x){
    unsigned r; asm("cvt.rna.tf32.f32 %0, %1;" : "=r"(r) : "f"(x)); return r;
}
__device__ __forceinline__ void mma_tf32(float c[4],
    unsigned a0, unsigned a1, unsigned a2, unsigned a3,
    unsigned b0, unsigned b1)
{
    asm volatile(
        "mma.sync.aligned.m16n8k8.row.col.f32.tf32.tf32.f32 "
        "{%0,%1,%2,%3}, {%4,%5,%6,%7}, {%8,%9}, {%0,%1,%2,%3};"
        : "+f"(c[0]), "+f"(c[1]), "+f"(c[2]), "+f"(c[3])
        : "r"(a0), "r"(a1), "r"(a2), "r"(a3), "r"(b0), "r"(b1));
}
// accurate fast tanh: MUFU.EX2 + approx divide (rel err ~2^-21), exact saturation
__device__ __forceinline__ float tanh_fast(float x){
    x = fminf(20.f, fmaxf(-20.f, x));
    float e = __expf(2.f*x);
    return __fdividef(e - 1.f, e + 1.f);
}

// ---------------- kernel 0: proj_dec = decoder_state @ W_s ----------------
__global__ void pd_kernel(const float* __restrict__ dec, const float* __restrict__ Ws){
    __shared__ float sd[EH];
    const int b = blockIdx.x, tid = threadIdx.x;
    for (int i = tid; i < EH; i += 256) sd[i] = dec[b*EH + i];
    __syncthreads();
    float a0 = 0.f, a1 = 0.f;
    const int c0 = tid, c1 = tid + 256;
    #pragma unroll 4
    for (int k = 0; k < EH; k++){
        float dv = sd[k];
        a0 += dv * Ws[k*AT + c0];
        a1 += dv * Ws[k*AT + c1];
    }
    g_pd[b*AT + c0] = a0;
    g_pd[b*AT + c1] = a1;
}

// ---------------- kernel 1: fused tf32 GEMM + tanh·v + local softmax + context partial ----
__global__ __launch_bounds__(256) void score_ctx_kernel(
    const float* __restrict__ E, const int* __restrict__ mask,
    const float* __restrict__ Wh, const float* __restrict__ v)
{
    __shared__ unsigned sE[BM*36];    // [row][k], stride 36 (conflict-free frag reads)
    __shared__ unsigned sW[BK*136];   // [k][col], stride 136
    __shared__ float sPd[AT], sV[AT];
    __shared__ float sScore[BM], sWgt[BM], sRed[BM];

    const int tid  = threadIdx.x;
    const int lane = tid & 31, warp = tid >> 5;
    const int g = lane >> 2, tig = lane & 3;
    const int mBase = (warp >> 2) * 64;   // 2 warps in M
    const int nBase = (warp & 3) * 32;    // 4 warps in N
    const int b = blockIdx.y, chunk = blockIdx.x;
    const int s0 = chunk * BM;

    for (int i = tid; i < AT; i += 256){ sPd[i] = g_pd[b*AT + i]; sV[i] = v[i]; }
    if (tid < BM) sScore[tid] = 0.f;

    const float* Eb = E + ((long)b*S_ + s0) * EH;

    float rowsum[8];
    #pragma unroll
    for (int j = 0; j < 8; j++) rowsum[j] = 0.f;

    for (int nch = 0; nch < NCHUNK; nch++){
        const int n0 = nch * BNC;
        float c[4][4][4];
        #pragma unroll
        for (int mt = 0; mt < 4; mt++)
            #pragma unroll
            for (int nt = 0; nt < 4; nt++)
                #pragma unroll
                for (int r = 0; r < 4; r++) c[mt][nt][r] = 0.f;

        for (int kc = 0; kc < EH/BK; kc++){
            __syncthreads();
            // stage E tile 128x32 -> sE[row][k] (tf32-converted)
            #pragma unroll
            for (int i = 0; i < 4; i++){
                int idx = tid + i*256;
                int row = idx >> 3, c4 = idx & 7;
                float4 ev = *(const float4*)(Eb + (long)row*EH + kc*BK + c4*4);
                unsigned* p = &sE[row*36 + c4*4];
                p[0] = f2tf(ev.x); p[1] = f2tf(ev.y); p[2] = f2tf(ev.z); p[3] = f2tf(ev.w);
            }
            // stage W tile 32x128 -> sW[k][col]
            #pragma unroll
            for (int i = 0; i < 4; i++){
                int idx = tid + i*256;
                int kk = idx >> 5, c4 = idx & 31;
                float4 wv = *(const float4*)(Wh + (long)(kc*BK + kk)*AT + n0 + c4*4);
                unsigned* p = &sW[kk*136 + c4*4];
                p[0] = f2tf(wv.x); p[1] = f2tf(wv.y); p[2] = f2tf(wv.z); p[3] = f2tf(wv.w);
            }
            __syncthreads();

            #pragma unroll
            for (int ks = 0; ks < 4; ks++){
                const int kk = ks*8 + tig;
                unsigned a[4][4];
                #pragma unroll
                for (int mt = 0; mt < 4; mt++){
                    int r0 = mBase + mt*16 + g;
                    a[mt][0] = sE[r0*36 + kk];
                    a[mt][1] = sE[(r0+8)*36 + kk];
                    a[mt][2] = sE[r0*36 + kk + 4];
                    a[mt][3] = sE[(r0+8)*36 + kk + 4];
                }
                unsigned bb[4][2];
                #pragma unroll
                for (int nt = 0; nt < 4; nt++){
                    int cc = nBase + nt*8 + g;
                    bb[nt][0] = sW[kk*136 + cc];
                    bb[nt][1] = sW[(kk+4)*136 + cc];
                }
                #pragma unroll
                for (int mt = 0; mt < 4; mt++)
                    #pragma unroll
                    for (int nt = 0; nt < 4; nt++)
                        mma_tf32(c[mt][nt], a[mt][0], a[mt][1], a[mt][2], a[mt][3],
                                 bb[nt][0], bb[nt][1]);
            }
        }

        // fused epilogue for this n-chunk: tanh(acc + pd) * v, accumulate per-row
        #pragma unroll
        for (int mt = 0; mt < 4; mt++){
            #pragma unroll
            for (int nt = 0; nt < 4; nt++){
                int cbase = n0 + nBase + nt*8 + 2*tig;
                #pragma unroll
                for (int r = 0; r < 4; r++){
                    int col = cbase + (r & 1);
                    float x = c[mt][nt][r] + sPd[col];
                    rowsum[mt*2 + (r >> 1)] += tanh_fast(x) * sV[col];
                }
            }
        }
    }

    // reduce over tig (4 lanes share a row-element group)
    #pragma unroll
    for (int j = 0; j < 8; j++){
        rowsum[j] += __shfl_xor_sync(0xffffffffu, rowsum[j], 1);
        rowsum[j] += __shfl_xor_sync(0xffffffffu, rowsum[j], 2);
    }
    if (tig == 0){
        #pragma unroll
        for (int j = 0; j < 8; j++){
            int row = mBase + (j >> 1)*16 + (j & 1)*8 + g;
            atomicAdd(&sScore[row], rowsum[j]);
        }
    }
    __syncthreads();

    // mask + store scores + local softmax stats
    float sc = 0.f; int mk = 0;
    if (tid < BM){
        mk = mask[b*S_ + s0 + tid];
        sc = mk ? sScore[tid] : -FLT_MAX;
        g_scores[b*S_ + s0 + tid] = sc;
        sRed[tid] = sc;
    }
    __syncthreads();
    for (int off = 64; off > 0; off >>= 1){
        if (tid < off) sRed[tid] = fmaxf(sRed[tid], sRed[tid + off]);
        __syncthreads();
    }
    const float lmax = sRed[0];
    __syncthreads();
    if (tid < BM){
        float w = mk ? __expf(sc - lmax) : 0.f;
        sWgt[tid] = w;
        sRed[tid] = w;
    }
    __syncthreads();
    for (int off = 64; off > 0; off >>= 1){
        if (tid < off) sRed[tid] += sRed[tid + off];
        __syncthreads();
    }
    if (tid == 0){
        g_lmax[b*CHUNKS + chunk] = lmax;
        g_lsum[b*CHUNKS + chunk] = sRed[0];
    }

    // context partial: sum_rows w[row] * E[row, :]  (E tile should be L2-hot)
    float4 acc = make_float4(0.f, 0.f, 0.f, 0.f);
    const float4* E4 = (const float4*)Eb;
    #pragma unroll 4
    for (int row = 0; row < BM; row++){
        float wv = sWgt[row];
        float4 ev = E4[row*(EH/4) + tid];
        acc.x += wv*ev.x; acc.y += wv*ev.y; acc.z += wv*ev.z; acc.w += wv*ev.w;
    }
    ((float4*)g_ctx)[(b*CHUNKS + chunk)*(EH/4) + tid] = acc;
}

// ---------------- kernel 2: merge chunk partials -> context + global stats ---------
__global__ void combine_kernel(float* __restrict__ out){
    __shared__ float sLm[CHUNKS], sLs[CHUNKS];
    const int b = blockIdx.x, tid = threadIdx.x;
    if (tid < CHUNKS){
        sLm[tid] = g_lmax[b*CHUNKS + tid];
        sLs[tid] = g_lsum[b*CHUNKS + tid];
    }
    __syncthreads();
    float gm = -FLT_MAX;
    #pragma unroll
    for (int c2 = 0; c2 < CHUNKS; c2++) gm = fmaxf(gm, sLm[c2]);
    float Z = 0.f;
    #pragma unroll
    for (int c2 = 0; c2 < CHUNKS; c2++) Z += sLs[c2] * __expf(sLm[c2] - gm);
    const float invZ = 1.0f / Z;
    if (tid == 0){ g_gmax[b] = gm; g_invZ[b] = invZ; }

    float4 acc = make_float4(0.f, 0.f, 0.f, 0.f);
    for (int c2 = 0; c2 < CHUNKS; c2++){
        float f = __expf(sLm[c2] - gm);
        float4 p = ((const float4*)g_ctx)[(b*CHUNKS + c2)*(EH/4) + tid];
        acc.x += f*p.x; acc.y += f*p.y; acc.z += f*p.z; acc.w += f*p.w;
    }
    acc.x *= invZ; acc.y *= invZ; acc.z *= invZ; acc.w *= invZ;
    ((float4*)out)[b*(EH/4) + tid] = acc;   // context first in output
}

// ---------------- kernel 3: weights = exp(score - gmax) / Z ----------------
__global__ void weights_kernel(float* __restrict__ out){
    const int i = blockIdx.x*256 + threadIdx.x;
    const int b = i >> 12;
    float w = __expf(g_scores[i] - g_gmax[b]) * g_invZ[b];  // masked -> exp(-huge) = 0
    out[B_*EH + i] = w;
}

// ---------------- launch ----------------
extern "C" void kernel_launch(void* const* d_in, const int* in_sizes, int n_in,
                              void* d_out, int out_size)
{
    const float* dec  = (const float*)d_in[0];  // (32,1024)
    const float* E    = (const float*)d_in[1];  // (32,4096,1024)
    const int*   mask = (const int*)  d_in[2];  // (32,4096)
    const float* Wh   = (const float*)d_in[3];  // (1024,512)
    const float* Ws   = (const float*)d_in[4];  // (1024,512)
    const float* v    = (const float*)d_in[5];  // (512,)
    float* out = (float*)d_out;                 // context (32*1024) ++ weights (32*4096)

    pd_kernel<<<B_, 256>>>(dec, Ws);
    score_ctx_kernel<<<dim3(CHUNKS, B_), 256>>>(E, mask, Wh, v);
    combine_kernel<<<B_, 256>>>(out);
    weights_kernel<<<(B_*S_)/256, 256>>>(out);
}

// round 14
// speedup vs baseline: 1.2414x; 1.2414x over previous
#include <cuda_runtime.h>
#include <cstdint>
#include <float.h>

#define B_      32
#define S_      4096
#define EH      1024
#define AT      512
#define BM      128
#define BK      32
#define NCHUNK  4
#define BNC     128
#define CHUNKS  (S_/BM)   // 32
#define KITERS  (EH/BK)   // 32

// dynamic smem layout (in 32-bit words)
#define SE_BUF   (BM*36)                 // 4608 words per buffer
#define SW_OFF   (2*SE_BUF)              // 9216
#define SW_BUF   (BK*136)                // 4352 words per buffer
#define PD_OFF   (SW_OFF + 2*SW_BUF)     // 17920
#define V_OFF    (PD_OFF + AT)
#define SC_OFF   (V_OFF + AT)
#define WG_OFF   (SC_OFF + BM)
#define RD_OFF   (WG_OFF + BM)
#define SMEM_WORDS (RD_OFF + BM)         // 19328
#define SMEM_BYTES (SMEM_WORDS*4)        // 77312

// ---------------- scratch (no allocations allowed) ----------------
__device__ float g_pd[B_*AT];
__device__ float g_scores[B_*S_];
__device__ float g_ctx[B_*CHUNKS*EH];
__device__ float g_lmax[B_*CHUNKS];
__device__ float g_lsum[B_*CHUNKS];
__device__ float g_gmax[B_];
__device__ float g_invZ[B_];

// ---------------- helpers ----------------
__device__ __forceinline__ void mma_tf32(float c[4],
    unsigned a0, unsigned a1, unsigned a2, unsigned a3,
    unsigned b0, unsigned b1)
{
    asm volatile(
        "mma.sync.aligned.m16n8k8.row.col.f32.tf32.tf32.f32 "
        "{%0,%1,%2,%3}, {%4,%5,%6,%7}, {%8,%9}, {%0,%1,%2,%3};"
        : "+f"(c[0]), "+f"(c[1]), "+f"(c[2]), "+f"(c[3])
        : "r"(a0), "r"(a1), "r"(a2), "r"(a3), "r"(b0), "r"(b1));
}
__device__ __forceinline__ void cpa16(const unsigned* sp, const float* gp){
    unsigned sa = (unsigned)__cvta_generic_to_shared((void*)sp);
    asm volatile("cp.async.cg.shared.global [%0], [%1], 16;" :: "r"(sa), "l"(gp));
}
__device__ __forceinline__ void cpa_commit(){
    asm volatile("cp.async.commit_group;" ::: "memory");
}
__device__ __forceinline__ void cpa_wait0(){
    asm volatile("cp.async.wait_group 0;" ::: "memory");
}
__device__ __forceinline__ float tanh_fast(float x){
    x = fminf(20.f, fmaxf(-20.f, x));
    float e = __expf(2.f*x);
    return __fdividef(e - 1.f, e + 1.f);
}

// ---------------- kernel 0: proj_dec = decoder_state @ W_s ----------------
__global__ void pd_kernel(const float* __restrict__ dec, const float* __restrict__ Ws){
    __shared__ float sd[EH];
    const int b = blockIdx.x, tid = threadIdx.x;
    for (int i = tid; i < EH; i += 256) sd[i] = dec[b*EH + i];
    __syncthreads();
    float a0 = 0.f, a1 = 0.f;
    const int c0 = tid, c1 = tid + 256;
    #pragma unroll 4
    for (int k = 0; k < EH; k++){
        float dv = sd[k];
        a0 += dv * Ws[k*AT + c0];
        a1 += dv * Ws[k*AT + c1];
    }
    g_pd[b*AT + c0] = a0;
    g_pd[b*AT + c1] = a1;
}

// ---------------- kernel 1: pipelined tf32 GEMM + tanh·v + softmax + context partial ----
__global__ __launch_bounds__(256, 2) void score_ctx_kernel(
    const float* __restrict__ E, const int* __restrict__ mask,
    const float* __restrict__ Wh, const float* __restrict__ v)
{
    extern __shared__ unsigned smem[];
    unsigned* sE = smem;                       // [2][BM*36]  stride 36, conflict-free frags
    unsigned* sW = smem + SW_OFF;              // [2][BK*136] stride 136
    float* sPd    = (float*)(smem + PD_OFF);
    float* sV     = (float*)(smem + V_OFF);
    float* sScore = (float*)(smem + SC_OFF);
    float* sWgt   = (float*)(smem + WG_OFF);
    float* sRed   = (float*)(smem + RD_OFF);

    const int tid  = threadIdx.x;
    const int lane = tid & 31, warp = tid >> 5;
    const int g = lane >> 2, tig = lane & 3;
    const int mBase = (warp >> 2) * 64;
    const int nBase = (warp & 3) * 32;
    const int b = blockIdx.y, chunk = blockIdx.x;
    const int s0 = chunk * BM;

    for (int i = tid; i < AT; i += 256){ sPd[i] = g_pd[b*AT + i]; sV[i] = v[i]; }
    if (tid < BM) sScore[tid] = 0.f;

    const float* Eb = E + ((long)b*S_ + s0) * EH;

    // staging index decomposition (idx = tid + i*256)
    const int erow = tid >> 3, ec4 = tid & 7;    // E: row = erow+32i, col4 = ec4
    const int wkk  = tid >> 5, wc4 = tid & 31;   // W: kk = wkk+8i, col4 = wc4

    float rowsum[8];
    #pragma unroll
    for (int j = 0; j < 8; j++) rowsum[j] = 0.f;

    for (int nch = 0; nch < NCHUNK; nch++){
        const int n0 = nch * BNC;
        float c[4][4][4];
        #pragma unroll
        for (int mt = 0; mt < 4; mt++)
            #pragma unroll
            for (int nt = 0; nt < 4; nt++)
                #pragma unroll
                for (int r = 0; r < 4; r++) c[mt][nt][r] = 0.f;

        // prologue: stage kc=0 into buffer 0
        {
            #pragma unroll
            for (int i = 0; i < 4; i++)
                cpa16(&sE[(erow + 32*i)*36 + ec4*4],
                      Eb + (long)(erow + 32*i)*EH + ec4*4);
            #pragma unroll
            for (int i = 0; i < 4; i++)
                cpa16(&sW[(wkk + 8*i)*136 + wc4*4],
                      Wh + (long)(wkk + 8*i)*AT + n0 + wc4*4);
            cpa_commit();
        }

        for (int kc = 0; kc < KITERS; kc++){
            cpa_wait0();
            __syncthreads();

            if (kc + 1 < KITERS){
                unsigned* nE = sE + ((kc+1)&1)*SE_BUF;
                unsigned* nW = sW + ((kc+1)&1)*SW_BUF;
                #pragma unroll
                for (int i = 0; i < 4; i++)
                    cpa16(&nE[(erow + 32*i)*36 + ec4*4],
                          Eb + (long)(erow + 32*i)*EH + (kc+1)*BK + ec4*4);
                #pragma unroll
                for (int i = 0; i < 4; i++)
                    cpa16(&nW[(wkk + 8*i)*136 + wc4*4],
                          Wh + (long)((kc+1)*BK + wkk + 8*i)*AT + n0 + wc4*4);
                cpa_commit();
            }

            const unsigned* bE = sE + (kc&1)*SE_BUF;
            const unsigned* bW = sW + (kc&1)*SW_BUF;

            #pragma unroll
            for (int ks = 0; ks < 4; ks++){
                const int kk = ks*8 + tig;
                unsigned a[4][4];
                #pragma unroll
                for (int mt = 0; mt < 4; mt++){
                    int r0 = mBase + mt*16 + g;
                    a[mt][0] = bE[r0*36 + kk];
                    a[mt][1] = bE[(r0+8)*36 + kk];
                    a[mt][2] = bE[r0*36 + kk + 4];
                    a[mt][3] = bE[(r0+8)*36 + kk + 4];
                }
                unsigned bb[4][2];
                #pragma unroll
                for (int nt = 0; nt < 4; nt++){
                    int cc = nBase + nt*8 + g;
                    bb[nt][0] = bW[kk*136 + cc];
                    bb[nt][1] = bW[(kk+4)*136 + cc];
                }
                #pragma unroll
                for (int mt = 0; mt < 4; mt++)
                    #pragma unroll
                    for (int nt = 0; nt < 4; nt++)
                        mma_tf32(c[mt][nt], a[mt][0], a[mt][1], a[mt][2], a[mt][3],
                                 bb[nt][0], bb[nt][1]);
            }
        }

        // fused epilogue: tanh(acc + pd) * v, accumulate per-row
        #pragma unroll
        for (int mt = 0; mt < 4; mt++){
            #pragma unroll
            for (int nt = 0; nt < 4; nt++){
                int cbase = n0 + nBase + nt*8 + 2*tig;
                #pragma unroll
                for (int r = 0; r < 4; r++){
                    int col = cbase + (r & 1);
                    float x = c[mt][nt][r] + sPd[col];
                    rowsum[mt*2 + (r >> 1)] += tanh_fast(x) * sV[col];
                }
            }
        }
    }

    // reduce over tig
    #pragma unroll
    for (int j = 0; j < 8; j++){
        rowsum[j] += __shfl_xor_sync(0xffffffffu, rowsum[j], 1);
        rowsum[j] += __shfl_xor_sync(0xffffffffu, rowsum[j], 2);
    }
    if (tig == 0){
        #pragma unroll
        for (int j = 0; j < 8; j++){
            int row = mBase + (j >> 1)*16 + (j & 1)*8 + g;
            atomicAdd(&sScore[row], rowsum[j]);
        }
    }
    __syncthreads();

    // mask + scores + local softmax stats
    float sc = 0.f; int mk = 0;
    if (tid < BM){
        mk = mask[b*S_ + s0 + tid];
        sc = mk ? sScore[tid] : -FLT_MAX;
        g_scores[b*S_ + s0 + tid] = sc;
        sRed[tid] = sc;
    }
    __syncthreads();
    for (int off = 64; off > 0; off >>= 1){
        if (tid < off) sRed[tid] = fmaxf(sRed[tid], sRed[tid + off]);
        __syncthreads();
    }
    const float lmax = sRed[0];
    __syncthreads();
    if (tid < BM){
        float w = mk ? __expf(sc - lmax) : 0.f;
        sWgt[tid] = w;
        sRed[tid] = w;
    }
    __syncthreads();
    for (int off = 64; off > 0; off >>= 1){
        if (tid < off) sRed[tid] += sRed[tid + off];
        __syncthreads();
    }
    if (tid == 0){
        g_lmax[b*CHUNKS + chunk] = lmax;
        g_lsum[b*CHUNKS + chunk] = sRed[0];
    }

    // context partial (E tile L2-hot)
    float4 acc = make_float4(0.f, 0.f, 0.f, 0.f);
    const float4* E4 = (const float4*)Eb;
    #pragma unroll 4
    for (int row = 0; row < BM; row++){
        float wv = sWgt[row];
        float4 ev = E4[row*(EH/4) + tid];
        acc.x += wv*ev.x; acc.y += wv*ev.y; acc.z += wv*ev.z; acc.w += wv*ev.w;
    }
    ((float4*)g_ctx)[(b*CHUNKS + chunk)*(EH/4) + tid] = acc;
}

// ---------------- kernel 2: merge chunk partials ----------------
__global__ void combine_kernel(float* __restrict__ out){
    __shared__ float sLm[CHUNKS], sLs[CHUNKS];
    const int b = blockIdx.x, tid = threadIdx.x;
    if (tid < CHUNKS){
        sLm[tid] = g_lmax[b*CHUNKS + tid];
        sLs[tid] = g_lsum[b*CHUNKS + tid];
    }
    __syncthreads();
    float gm = -FLT_MAX;
    #pragma unroll
    for (int c2 = 0; c2 < CHUNKS; c2++) gm = fmaxf(gm, sLm[c2]);
    float Z = 0.f;
    #pragma unroll
    for (int c2 = 0; c2 < CHUNKS; c2++) Z += sLs[c2] * __expf(sLm[c2] - gm);
    const float invZ = 1.0f / Z;
    if (tid == 0){ g_gmax[b] = gm; g_invZ[b] = invZ; }

    float4 acc = make_float4(0.f, 0.f, 0.f, 0.f);
    for (int c2 = 0; c2 < CHUNKS; c2++){
        float f = __expf(sLm[c2] - gm);
        float4 p = ((const float4*)g_ctx)[(b*CHUNKS + c2)*(EH/4) + tid];
        acc.x += f*p.x; acc.y += f*p.y; acc.z += f*p.z; acc.w += f*p.w;
    }
    acc.x *= invZ; acc.y *= invZ; acc.z *= invZ; acc.w *= invZ;
    ((float4*)out)[b*(EH/4) + tid] = acc;
}

// ---------------- kernel 3: weights ----------------
__global__ void weights_kernel(float* __restrict__ out){
    const int i = blockIdx.x*256 + threadIdx.x;
    const int b = i >> 12;
    float w = __expf(g_scores[i] - g_gmax[b]) * g_invZ[b];
    out[B_*EH + i] = w;
}

// ---------------- launch ----------------
extern "C" void kernel_launch(void* const* d_in, const int* in_sizes, int n_in,
                              void* d_out, int out_size)
{
    const float* dec  = (const float*)d_in[0];
    const float* E    = (const float*)d_in[1];
    const int*   mask = (const int*)  d_in[2];
    const float* Wh   = (const float*)d_in[3];
    const float* Ws   = (const float*)d_in[4];
    const float* v    = (const float*)d_in[5];
    float* out = (float*)d_out;

    cudaFuncSetAttribute(score_ctx_kernel,
                         cudaFuncAttributeMaxDynamicSharedMemorySize, SMEM_BYTES);

    pd_kernel<<<B_, 256>>>(dec, Ws);
    score_ctx_kernel<<<dim3(CHUNKS, B_), 256, SMEM_BYTES>>>(E, mask, Wh, v);
    combine_kernel<<<B_, 256>>>(out);
    weights_kernel<<<(B_*S_)/256, 256>>>(out);
}